// round 1
// baseline (speedup 1.0000x reference)
#include <cuda_runtime.h>

#define H 51
#define H3 153
#define PITCH 52          // padded row length (words); 52*4B = 208B, 16B-aligned rows
#define BB 16             // batches per CTA
#define NB 4              // batches per thread
#define NGROUP (BB/NB)    // 4
#define NTASK (H*NGROUP)  // 204 compute threads
#define NTHREADS 224
#define NK 13             // float4 chunks per padded row (52/4)

__device__ __forceinline__ float sigf(float v) {
    return __fdividef(1.0f, 1.0f + __expf(-v));
}
__device__ __forceinline__ float tanh_f(float v) {
    // tanh(v) = 1 - 2/(exp(2v)+1); exact at saturation, ~1e-7 abs error
    return 1.0f - __fdividef(2.0f, __expf(2.0f * v) + 1.0f);
}
__device__ __forceinline__ float dot4(float4 w, float4 h, float acc) {
    acc = fmaf(w.x, h.x, acc);
    acc = fmaf(w.y, h.y, acc);
    acc = fmaf(w.z, h.z, acc);
    acc = fmaf(w.w, h.w, acc);
    return acc;
}

__global__ __launch_bounds__(NTHREADS, 1)
void gru2_kernel(const float* __restrict__ input,
                 const float* __restrict__ w_ih1, const float* __restrict__ w_hh1,
                 const float* __restrict__ b_ih1, const float* __restrict__ b_hh1,
                 const float* __restrict__ w_ih2, const float* __restrict__ w_hh2,
                 const float* __restrict__ b_ih2, const float* __restrict__ b_hh2,
                 const float* __restrict__ w_lin, const float* __restrict__ b_lin,
                 float* __restrict__ out, int T, int F)
{
    extern __shared__ float sm[];
    float* whh1s = sm;                       // [153][52]
    float* wih2s = whh1s + H3 * PITCH;       // [153][52]
    float* whh2s = wih2s + H3 * PITCH;       // [153][52]
    float* h1s   = whh2s + H3 * PITCH;       // [2][BB][52]
    float* h2s   = h1s + 2 * BB * PITCH;     // [2][BB][52]
    float* oacc  = h2s + 2 * BB * PITCH;     // [2][BB]

    const int tid = threadIdx.x;
    const int gb0 = blockIdx.x * BB;
    const int TOT = T + F;

    // Stage weights into shared (padded column 51 = 0 so float4 tails are inert)
    for (int i = tid; i < H3 * PITCH; i += NTHREADS) {
        int r = i / PITCH, c = i - r * PITCH;
        float v1 = 0.f, v2 = 0.f, v3 = 0.f;
        if (c < H) {
            v1 = w_hh1[r * H + c];
            v2 = w_ih2[r * H + c];
            v3 = w_hh2[r * H + c];
        }
        whh1s[i] = v1; wih2s[i] = v2; whh2s[i] = v3;
    }
    for (int i = tid; i < 2 * BB * PITCH; i += NTHREADS) { h1s[i] = 0.f; h2s[i] = 0.f; }
    if (tid < 2 * BB) oacc[tid] = 0.f;

    const bool active = (tid < NTASK);
    int u = 0, bloc = 0;
    float wi1r = 0, wi1z = 0, wi1n = 0, c1r = 0, c1z = 0, bi1n = 0, bh1n = 0;
    float c2r = 0, c2z = 0, bi2n = 0, bh2n = 0, wlu = 0;
    if (active) {
        u = tid % H;
        bloc = (tid / H) * NB;
        wi1r = __ldg(&w_ih1[u]);
        wi1z = __ldg(&w_ih1[H + u]);
        wi1n = __ldg(&w_ih1[2 * H + u]);
        c1r  = __ldg(&b_ih1[u]) + __ldg(&b_hh1[u]);
        c1z  = __ldg(&b_ih1[H + u]) + __ldg(&b_hh1[H + u]);
        bi1n = __ldg(&b_ih1[2 * H + u]);
        bh1n = __ldg(&b_hh1[2 * H + u]);
        c2r  = __ldg(&b_ih2[u]) + __ldg(&b_hh2[u]);
        c2z  = __ldg(&b_ih2[H + u]) + __ldg(&b_hh2[H + u]);
        bi2n = __ldg(&b_ih2[2 * H + u]);
        bh2n = __ldg(&b_hh2[2 * H + u]);
        wlu  = __ldg(&w_lin[u]);
    }
    const float blin = __ldg(&b_lin[0]);
    __syncthreads();

    for (int t = 0; t < TOT; ++t) {
        const int cur = t & 1, nxt = cur ^ 1;
        float* h1cur = h1s + cur * BB * PITCH;
        float* h1nxt = h1s + nxt * BB * PITCH;
        float* h2cur = h2s + cur * BB * PITCH;
        float* h2nxt = h2s + nxt * BB * PITCH;
        float* oa_w  = oacc + cur * BB;   // filled in phase B this step
        float* oa_r  = oacc + nxt * BB;   // holds o_{t-1} (sans b_lin)

        // ---------------- Phase A: layer-1 GRU cell ----------------
        if (!active) {
            int j = tid - NTASK;          // helper threads: 0..19
            if (j < BB) {
                if (t > 0) out[(gb0 + j) * TOT + (t - 1)] = oa_r[j] + blin;
                oa_w[j] = 0.f;            // zero accumulator for this step
            }
        } else {
            float x[NB];
            #pragma unroll
            for (int bi = 0; bi < NB; ++bi) {
                int b = bloc + bi;
                x[bi] = (t < T) ? __ldg(&input[(size_t)(gb0 + b) * T + t])
                                : (oa_r[b] + blin);
            }
            float ar[NB], az[NB], an[NB];
            #pragma unroll
            for (int bi = 0; bi < NB; ++bi) { ar[bi] = 0.f; az[bi] = 0.f; an[bi] = 0.f; }

            const float4* wr = (const float4*)(whh1s + u * PITCH);
            const float4* wz = (const float4*)(whh1s + (H + u) * PITCH);
            const float4* wn = (const float4*)(whh1s + (2 * H + u) * PITCH);
            const float4* hb = (const float4*)(h1cur + bloc * PITCH);

            #pragma unroll
            for (int k = 0; k < NK; ++k) {
                float4 a = wr[k], b4 = wz[k], c4 = wn[k];
                #pragma unroll
                for (int bi = 0; bi < NB; ++bi) {
                    float4 h4 = hb[bi * NK + k];
                    ar[bi] = dot4(a,  h4, ar[bi]);
                    az[bi] = dot4(b4, h4, az[bi]);
                    an[bi] = dot4(c4, h4, an[bi]);
                }
            }
            #pragma unroll
            for (int bi = 0; bi < NB; ++bi) {
                int b = bloc + bi;
                float r = sigf(fmaf(x[bi], wi1r, c1r + ar[bi]));
                float z = sigf(fmaf(x[bi], wi1z, c1z + az[bi]));
                float n = tanh_f(fmaf(x[bi], wi1n, bi1n) + r * (an[bi] + bh1n));
                float hold = h1cur[b * PITCH + u];
                h1nxt[b * PITCH + u] = n + z * (hold - n);   // (1-z)n + z h
            }
        }
        __syncthreads();

        // ---------------- Phase B: layer-2 GRU cell + output ----------------
        if (active) {
            float ar[NB], az[NB], ai[NB], ah[NB];
            #pragma unroll
            for (int bi = 0; bi < NB; ++bi) { ar[bi]=0.f; az[bi]=0.f; ai[bi]=0.f; ah[bi]=0.f; }

            const float4* wir = (const float4*)(wih2s + u * PITCH);
            const float4* wiz = (const float4*)(wih2s + (H + u) * PITCH);
            const float4* win = (const float4*)(wih2s + (2 * H + u) * PITCH);
            const float4* whr = (const float4*)(whh2s + u * PITCH);
            const float4* whz = (const float4*)(whh2s + (H + u) * PITCH);
            const float4* whn = (const float4*)(whh2s + (2 * H + u) * PITCH);
            const float4* h1b = (const float4*)(h1nxt + bloc * PITCH);
            const float4* h2b = (const float4*)(h2cur + bloc * PITCH);

            #pragma unroll
            for (int k = 0; k < NK; ++k) {
                float4 wa = wir[k], wb = wiz[k], wc = win[k];
                float4 wd = whr[k], we = whz[k], wf = whn[k];
                #pragma unroll
                for (int bi = 0; bi < NB; ++bi) {
                    float4 p = h1b[bi * NK + k];
                    float4 q = h2b[bi * NK + k];
                    ar[bi] = dot4(wa, p, ar[bi]);
                    ar[bi] = dot4(wd, q, ar[bi]);
                    az[bi] = dot4(wb, p, az[bi]);
                    az[bi] = dot4(we, q, az[bi]);
                    ai[bi] = dot4(wc, p, ai[bi]);
                    ah[bi] = dot4(wf, q, ah[bi]);
                }
            }
            #pragma unroll
            for (int bi = 0; bi < NB; ++bi) {
                int b = bloc + bi;
                float r = sigf(ar[bi] + c2r);
                float z = sigf(az[bi] + c2z);
                float n = tanh_f(ai[bi] + bi2n + r * (ah[bi] + bh2n));
                float hold = h2cur[b * PITCH + u];
                float hnew = n + z * (hold - n);
                h2nxt[b * PITCH + u] = hnew;
                atomicAdd(&oa_w[b], wlu * hnew);
            }
        }
        __syncthreads();
    }

    // Final timestep's output
    if (tid < BB) {
        out[(gb0 + tid) * TOT + (TOT - 1)] = oacc[((TOT - 1) & 1) * BB + tid] + blin;
    }
}

extern "C" void kernel_launch(void* const* d_in, const int* in_sizes, int n_in,
                              void* d_out, int out_size) {
    const float* input = (const float*)d_in[0];
    // d_in[1] is 'future' (scalar) — derived from out_size instead (no device read)
    const float* w_ih1 = (const float*)d_in[2];
    const float* w_hh1 = (const float*)d_in[3];
    const float* b_ih1 = (const float*)d_in[4];
    const float* b_hh1 = (const float*)d_in[5];
    const float* w_ih2 = (const float*)d_in[6];
    const float* w_hh2 = (const float*)d_in[7];
    const float* b_ih2 = (const float*)d_in[8];
    const float* b_hh2 = (const float*)d_in[9];
    const float* w_lin = (const float*)d_in[10];
    const float* b_lin = (const float*)d_in[11];

    const int B   = 2048;
    const int T   = in_sizes[0] / B;
    const int TOT = out_size / B;
    const int F   = TOT - T;

    size_t smem = (size_t)(3 * H3 * PITCH + 4 * BB * PITCH + 2 * BB) * sizeof(float);
    cudaFuncSetAttribute(gru2_kernel, cudaFuncAttributeMaxDynamicSharedMemorySize, (int)smem);

    gru2_kernel<<<B / BB, NTHREADS, smem>>>(
        input, w_ih1, w_hh1, b_ih1, b_hh1,
        w_ih2, w_hh2, b_ih2, b_hh2,
        w_lin, b_lin, (float*)d_out, T, F);
}

// round 2
// speedup vs baseline: 1.0610x; 1.0610x over previous
#include <cuda_runtime.h>

#define H 51
#define H3 153
#define WP 72      // weight row pitch in words (72 mod 32 = 8 -> conflict-free with HOFF)
#define HOFF 36    // word offset of half-1 k-range inside a weight row (36 mod 32 = 4)
#define HP 56      // h row pitch in words (words 51..55 stay zero)
#define NCH 7      // float4 chunks per half (covers k 0..27 / 28..55, tail zero-padded)
#define BB 16      // batches per CTA
#define NB 4       // batches per pair
#define NPAIR 204  // (unit, quad) pairs: 51 * 4
#define NACT 408   // compute threads (2 per pair)
#define NTHREADS 448

__device__ __forceinline__ float sigf(float v) {
    return __fdividef(1.0f, 1.0f + __expf(-v));
}
__device__ __forceinline__ float tanh_f(float v) {
    return 1.0f - __fdividef(2.0f, __expf(2.0f * v) + 1.0f);
}
__device__ __forceinline__ float dot4(float4 w, float4 h, float acc) {
    acc = fmaf(w.x, h.x, acc);
    acc = fmaf(w.y, h.y, acc);
    acc = fmaf(w.z, h.z, acc);
    acc = fmaf(w.w, h.w, acc);
    return acc;
}

__global__ __launch_bounds__(NTHREADS, 1)
void gru2_kernel(const float* __restrict__ input,
                 const float* __restrict__ w_ih1, const float* __restrict__ w_hh1,
                 const float* __restrict__ b_ih1, const float* __restrict__ b_hh1,
                 const float* __restrict__ w_ih2, const float* __restrict__ w_hh2,
                 const float* __restrict__ b_ih2, const float* __restrict__ b_hh2,
                 const float* __restrict__ w_lin, const float* __restrict__ b_lin,
                 float* __restrict__ out, int T, int F)
{
    extern __shared__ float sm[];
    float* whh1s = sm;                     // [153][WP]
    float* wih2s = whh1s + H3 * WP;        // [153][WP]
    float* whh2s = wih2s + H3 * WP;        // [153][WP]
    float* h1s   = whh2s + H3 * WP;        // [2][BB][HP]
    float* h2s   = h1s + 2 * BB * HP;      // [2][BB][HP]
    float* oacc  = h2s + 2 * BB * HP;      // [2][BB]

    const int tid = threadIdx.x;
    const int gb0 = blockIdx.x * BB;
    const int TOT = T + F;

    // Zero weights (for the padded tails) and h buffers
    for (int i = tid; i < 3 * H3 * WP; i += NTHREADS) sm[i] = 0.f;
    for (int i = tid; i < 4 * BB * HP; i += NTHREADS) h1s[i] = 0.f;
    if (tid < 2 * BB) oacc[tid] = 0.f;
    __syncthreads();

    // Scatter weights: k<28 at word k, k>=28 at word HOFF+(k-28)
    for (int i = tid; i < H3 * H; i += NTHREADS) {
        int r = i / H, k = i - r * H;
        int w = r * WP + (k < 28 ? k : HOFF + (k - 28));
        whh1s[w] = w_hh1[i];
        wih2s[w] = w_ih2[i];
        whh2s[w] = w_hh2[i];
    }

    const bool comp = (tid < NACT);
    const int p = tid >> 1;
    const int half = tid & 1;
    const unsigned pmask = 0x3u << (tid & 30);   // lane-pair shuffle mask

    int u = 0, bloc = 0;
    float wi1r = 0, wi1z = 0, wi1n = 0, c1r = 0, c1z = 0, bi1n = 0, bh1n = 0;
    float c2r = 0, c2z = 0, bi2n = 0, bh2n = 0, wlu = 0;
    if (comp) {
        u    = p % H;
        bloc = (p / H) * NB;
        wi1r = __ldg(&w_ih1[u]);
        wi1z = __ldg(&w_ih1[H + u]);
        wi1n = __ldg(&w_ih1[2 * H + u]);
        c1r  = __ldg(&b_ih1[u]) + __ldg(&b_hh1[u]);
        c1z  = __ldg(&b_ih1[H + u]) + __ldg(&b_hh1[H + u]);
        bi1n = __ldg(&b_ih1[2 * H + u]);
        bh1n = __ldg(&b_hh1[2 * H + u]);
        c2r  = __ldg(&b_ih2[u]) + __ldg(&b_hh2[u]);
        c2z  = __ldg(&b_ih2[H + u]) + __ldg(&b_hh2[H + u]);
        bi2n = __ldg(&b_ih2[2 * H + u]);
        bh2n = __ldg(&b_hh2[2 * H + u]);
        wlu  = __ldg(&w_lin[u]);
    }
    const float blin = __ldg(&b_lin[0]);

    // Weight chunk pointers (constant across steps)
    const float4* wAr = (const float4*)(whh1s + u * WP + half * HOFF);
    const float4* wAz = (const float4*)(whh1s + (H + u) * WP + half * HOFF);
    const float4* wAn = (const float4*)(whh1s + (2 * H + u) * WP + half * HOFF);
    const float4* wIr = (const float4*)(wih2s + u * WP + half * HOFF);
    const float4* wIz = (const float4*)(wih2s + (H + u) * WP + half * HOFF);
    const float4* wIn = (const float4*)(wih2s + (2 * H + u) * WP + half * HOFF);
    const float4* wHr = (const float4*)(whh2s + u * WP + half * HOFF);
    const float4* wHz = (const float4*)(whh2s + (H + u) * WP + half * HOFF);
    const float4* wHn = (const float4*)(whh2s + (2 * H + u) * WP + half * HOFF);

    __syncthreads();

    for (int t = 0; t < TOT; ++t) {
        const int cur = t & 1, nxt = cur ^ 1;
        float* h1cur = h1s + cur * BB * HP;
        float* h1nxt = h1s + nxt * BB * HP;
        float* h2cur = h2s + cur * BB * HP;
        float* h2nxt = h2s + nxt * BB * HP;
        float* oa_w  = oacc + cur * BB;   // accumulates o_t (phase B)
        float* oa_r  = oacc + nxt * BB;   // holds o_{t-1} (sans b_lin)

        // ---------------- Phase A: layer-1 GRU ----------------
        if (!comp) {
            int j = tid - NACT;
            if (j < BB) {
                if (t > 0) out[(size_t)(gb0 + j) * TOT + (t - 1)] = oa_r[j] + blin;
                oa_w[j] = 0.f;
            }
        } else {
            float x[NB];
            #pragma unroll
            for (int bi = 0; bi < NB; ++bi) {
                int b = bloc + bi;
                x[bi] = (t < T) ? __ldg(&input[(size_t)(gb0 + b) * T + t])
                                : (oa_r[b] + blin);
            }
            float ar[NB], az[NB], an[NB];
            #pragma unroll
            for (int bi = 0; bi < NB; ++bi) { ar[bi] = 0.f; az[bi] = 0.f; an[bi] = 0.f; }

            const float4* hA = (const float4*)(h1cur + bloc * HP) + half * NCH;
            #pragma unroll
            for (int k = 0; k < NCH; ++k) {
                float4 a = wAr[k], z4 = wAz[k], n4 = wAn[k];
                #pragma unroll
                for (int bi = 0; bi < NB; ++bi) {
                    float4 h4 = hA[bi * (HP / 4) + k];
                    ar[bi] = dot4(a,  h4, ar[bi]);
                    az[bi] = dot4(z4, h4, az[bi]);
                    an[bi] = dot4(n4, h4, an[bi]);
                }
            }
            #pragma unroll
            for (int bi = 0; bi < NB; ++bi) {
                ar[bi] += __shfl_xor_sync(pmask, ar[bi], 1);
                az[bi] += __shfl_xor_sync(pmask, az[bi], 1);
                an[bi] += __shfl_xor_sync(pmask, an[bi], 1);
            }
            #pragma unroll
            for (int bi = 0; bi < NB; ++bi) {
                int b = bloc + bi;
                float r = sigf(fmaf(x[bi], wi1r, c1r + ar[bi]));
                float z = sigf(fmaf(x[bi], wi1z, c1z + az[bi]));
                float n = tanh_f(fmaf(x[bi], wi1n, bi1n) + r * (an[bi] + bh1n));
                float hold = h1cur[b * HP + u];
                if (half == 0) h1nxt[b * HP + u] = n + z * (hold - n);
            }
        }
        __syncthreads();

        // ---------------- Phase B: layer-2 GRU + output ----------------
        if (comp) {
            float ar[NB], az[NB], ai[NB], ah[NB];
            #pragma unroll
            for (int bi = 0; bi < NB; ++bi) { ar[bi]=0.f; az[bi]=0.f; ai[bi]=0.f; ah[bi]=0.f; }

            const float4* h1b = (const float4*)(h1nxt + bloc * HP) + half * NCH;
            const float4* h2b = (const float4*)(h2cur + bloc * HP) + half * NCH;

            #pragma unroll
            for (int k = 0; k < NCH; ++k) {
                float4 wa = wIr[k], wb = wIz[k], wc = wIn[k];
                float4 wd = wHr[k], we = wHz[k], wf = wHn[k];
                #pragma unroll
                for (int bi = 0; bi < NB; ++bi) {
                    float4 pv = h1b[bi * (HP / 4) + k];
                    float4 qv = h2b[bi * (HP / 4) + k];
                    ar[bi] = dot4(wa, pv, ar[bi]);
                    ar[bi] = dot4(wd, qv, ar[bi]);
                    az[bi] = dot4(wb, pv, az[bi]);
                    az[bi] = dot4(we, qv, az[bi]);
                    ai[bi] = dot4(wc, pv, ai[bi]);
                    ah[bi] = dot4(wf, qv, ah[bi]);
                }
            }
            #pragma unroll
            for (int bi = 0; bi < NB; ++bi) {
                ar[bi] += __shfl_xor_sync(pmask, ar[bi], 1);
                az[bi] += __shfl_xor_sync(pmask, az[bi], 1);
                ai[bi] += __shfl_xor_sync(pmask, ai[bi], 1);
                ah[bi] += __shfl_xor_sync(pmask, ah[bi], 1);
            }
            #pragma unroll
            for (int bi = 0; bi < NB; ++bi) {
                int b = bloc + bi;
                float r = sigf(ar[bi] + c2r);
                float z = sigf(az[bi] + c2z);
                float n = tanh_f(ai[bi] + bi2n + r * (ah[bi] + bh2n));
                float hold = h2cur[b * HP + u];
                float hnew = n + z * (hold - n);
                if (half == 0) {
                    h2nxt[b * HP + u] = hnew;
                    atomicAdd(&oa_w[b], wlu * hnew);
                }
            }
        }
        __syncthreads();
    }

    if (tid < BB) {
        out[(size_t)(gb0 + tid) * TOT + (TOT - 1)] = oacc[((TOT - 1) & 1) * BB + tid] + blin;
    }
}

extern "C" void kernel_launch(void* const* d_in, const int* in_sizes, int n_in,
                              void* d_out, int out_size) {
    const float* input = (const float*)d_in[0];
    const float* w_ih1 = (const float*)d_in[2];
    const float* w_hh1 = (const float*)d_in[3];
    const float* b_ih1 = (const float*)d_in[4];
    const float* b_hh1 = (const float*)d_in[5];
    const float* w_ih2 = (const float*)d_in[6];
    const float* w_hh2 = (const float*)d_in[7];
    const float* b_ih2 = (const float*)d_in[8];
    const float* b_hh2 = (const float*)d_in[9];
    const float* w_lin = (const float*)d_in[10];
    const float* b_lin = (const float*)d_in[11];

    const int B   = 2048;
    const int T   = in_sizes[0] / B;
    const int TOT = out_size / B;
    const int F   = TOT - T;

    size_t smem = (size_t)(3 * H3 * WP + 4 * BB * HP + 2 * BB) * sizeof(float);
    cudaFuncSetAttribute(gru2_kernel, cudaFuncAttributeMaxDynamicSharedMemorySize, (int)smem);

    gru2_kernel<<<B / BB, NTHREADS, smem>>>(
        input, w_ih1, w_hh1, b_ih1, b_hh1,
        w_ih2, w_hh2, b_ih2, b_hh2,
        w_lin, b_lin, (float*)d_out, T, F);
}

// round 3
// speedup vs baseline: 1.1568x; 1.0902x over previous
#include <cuda_runtime.h>

#define H 51
#define HP 52            // h row pitch (words), 16B-aligned rows
#define BB 16            // batches per CTA
#define GP 17            // gbuf pitch (words) -> conflict-free
#define NROWS 459        // 153 (whh1) + 153 (whh2) + 153 (wih2)
#define NACT1 230        // stage-1 dot threads: 153 L1 + 77 hh2
#define NTHREADS 480
#define NUPD 816         // 51*16 pointwise tasks

#define FFMA2(d, a, b_) asm("fma.rn.f32x2 %0, %1, %2, %0;" : "+l"(d) : "l"(a), "l"(b_))

__device__ __forceinline__ unsigned long long pack2(float lo, float hi) {
    unsigned long long r;
    asm("mov.b64 %0, {%1,%2};" : "=l"(r) : "f"(lo), "f"(hi));
    return r;
}
__device__ __forceinline__ float2 unpack2(unsigned long long v) {
    float lo, hi;
    asm("mov.b64 {%0,%1}, %2;" : "=f"(lo), "=f"(hi) : "l"(v));
    return make_float2(lo, hi);
}
__device__ __forceinline__ float sigf(float v) {
    return __fdividef(1.0f, 1.0f + __expf(-v));
}
__device__ __forceinline__ float tanh_f(float v) {
    return 1.0f - __fdividef(2.0f, __expf(2.0f * v) + 1.0f);
}

// One row-thread: dot(w_row, h[b][:]) for all 16 batches; broadcast smem reads.
__device__ __forceinline__ void dot_row(const unsigned long long* w2,
                                        const float* __restrict__ hbase,
                                        const float* xv, float xc, float bias0,
                                        float* __restrict__ gout) {
    unsigned long long acc[BB];
    #pragma unroll
    for (int b = 0; b < BB; ++b) acc[b] = pack2(fmaf(xv[b], xc, bias0), 0.f);
    #pragma unroll
    for (int kc = 0; kc < 13; ++kc) {
        #pragma unroll
        for (int b = 0; b < BB; ++b) {
            ulonglong2 hv = *(const ulonglong2*)(hbase + b * HP + kc * 4);
            FFMA2(acc[b], w2[2 * kc],     hv.x);
            FFMA2(acc[b], w2[2 * kc + 1], hv.y);
        }
    }
    #pragma unroll
    for (int b = 0; b < BB; ++b) {
        float2 p = unpack2(acc[b]);
        gout[b] = p.x + p.y;
    }
}

__global__ __launch_bounds__(NTHREADS, 1)
void gru2_kernel(const float* __restrict__ input,
                 const float* __restrict__ w_ih1, const float* __restrict__ w_hh1,
                 const float* __restrict__ b_ih1, const float* __restrict__ b_hh1,
                 const float* __restrict__ w_ih2, const float* __restrict__ w_hh2,
                 const float* __restrict__ b_ih2, const float* __restrict__ b_hh2,
                 const float* __restrict__ w_lin, const float* __restrict__ b_lin,
                 float* __restrict__ out, int T, int F)
{
    extern __shared__ float sm[];
    float* h1s  = sm;                       // [2][BB][HP]
    float* h2s  = h1s + 2 * BB * HP;        // [2][BB][HP]
    float* gbuf = h2s + 2 * BB * HP;        // [459][GP]
    float* xbuf = gbuf + NROWS * GP;        // [BB]
    float* oacc = xbuf + BB;                // [2][BB]
    float* cWn  = oacc + 2 * BB;            // [51]
    float* cBn  = cWn + H;                  // [51]
    float* cWl  = cBn + H;                  // [51]

    const int tid = threadIdx.x;
    const int gb0 = blockIdx.x * BB;
    const int TOT = T + F;

    for (int i = tid; i < 4 * BB * HP; i += NTHREADS) sm[i] = 0.f;
    if (tid < 2 * BB) oacc[tid] = 0.f;
    if (tid < H) {
        cWn[tid] = __ldg(&w_ih1[2 * H + tid]);
        cBn[tid] = __ldg(&b_ih1[2 * H + tid]);
        cWl[tid] = __ldg(&w_lin[tid]);
    }

    // Per-row weights -> registers (26 packed f32x2)
    const float* wsrc = w_hh1;   // dummy default
    float bias0 = 0.f, xc = 0.f;
    if (tid < 153) {
        wsrc = w_hh1 + tid * H;
        if (tid < 102) { xc = __ldg(&w_ih1[tid]); bias0 = __ldg(&b_ih1[tid]) + __ldg(&b_hh1[tid]); }
        else           { xc = 0.f;                bias0 = __ldg(&b_hh1[tid]); }
    } else if (tid < 306) {
        wsrc = w_hh2 + (tid - 153) * H;
        bias0 = __ldg(&b_hh2[tid - 153]);
    } else if (tid < NROWS) {
        wsrc = w_ih2 + (tid - 306) * H;
        bias0 = __ldg(&b_ih2[tid - 306]);
    }
    unsigned long long w2[26];
    #pragma unroll
    for (int j = 0; j < 25; ++j) w2[j] = pack2(__ldg(&wsrc[2 * j]), __ldg(&wsrc[2 * j + 1]));
    w2[25] = pack2(__ldg(&wsrc[50]), 0.f);

    const float blin = __ldg(&b_lin[0]);
    __syncthreads();

    for (int t = 0; t < TOT; ++t) {
        const int cur = t & 1, nxt = cur ^ 1;
        float* h1cur = h1s + cur * BB * HP;
        float* h1nxt = h1s + nxt * BB * HP;
        float* h2cur = h2s + cur * BB * HP;
        float* h2nxt = h2s + nxt * BB * HP;
        float* oa_w  = oacc + cur * BB;   // o_t accumulator (stage 4)
        float* oa_r  = oacc + nxt * BB;   // o_{t-1} (sans b_lin)

        // ---- S1: L1 rows (x h1cur) + first 77 hh2 rows (x h2cur); helpers ----
        if (tid < NACT1) {
            float xv[BB];
            if (tid < 102) {
                #pragma unroll
                for (int b = 0; b < BB; ++b)
                    xv[b] = (t < T) ? __ldg(&input[(size_t)(gb0 + b) * T + t])
                                    : (oa_r[b] + blin);
            } else {
                #pragma unroll
                for (int b = 0; b < BB; ++b) xv[b] = 0.f;
            }
            const float* hbase = (tid < 153) ? h1cur : h2cur;
            dot_row(w2, hbase, xv, xc, bias0, gbuf + tid * GP);
        } else if (tid >= NROWS) {
            int j = tid - NROWS;
            if (j < BB) {
                if (t > 0) out[(size_t)(gb0 + j) * TOT + (t - 1)] = oa_r[j] + blin;
                oa_w[j] = 0.f;
                xbuf[j] = (t < T) ? __ldg(&input[(size_t)(gb0 + j) * T + t])
                                  : (oa_r[j] + blin);
            }
        }
        __syncthreads();

        // ---- S2: layer-1 pointwise update ----
        #pragma unroll
        for (int i = tid; i < NUPD; i += NTHREADS) {
            int b = i / H, u = i - b * H;
            float r  = sigf(gbuf[u * GP + b]);
            float z  = sigf(gbuf[(H + u) * GP + b]);
            float hn = gbuf[(2 * H + u) * GP + b];
            float i_n = fmaf(xbuf[b], cWn[u], cBn[u]);
            float n  = tanh_f(fmaf(r, hn, i_n));
            float hold = h1cur[b * HP + u];
            h1nxt[b * HP + u] = n + z * (hold - n);
        }
        __syncthreads();

        // ---- S3: remaining hh2 rows (x h2cur) + ih2 rows (x h1new) ----
        if (tid >= NACT1 && tid < NROWS) {
            float xv[BB];
            #pragma unroll
            for (int b = 0; b < BB; ++b) xv[b] = 0.f;
            const float* hbase = (tid < 306) ? h2cur : h1nxt;
            dot_row(w2, hbase, xv, 0.f, bias0, gbuf + tid * GP);
        }
        __syncthreads();

        // ---- S4: layer-2 pointwise update + output reduction ----
        #pragma unroll
        for (int i = tid; i < NUPD; i += NTHREADS) {
            int b = i / H, u = i - b * H;
            float air = gbuf[(306 + u) * GP + b];
            float aiz = gbuf[(357 + u) * GP + b];
            float ain = gbuf[(408 + u) * GP + b];
            float ahr = gbuf[(153 + u) * GP + b];
            float ahz = gbuf[(204 + u) * GP + b];
            float ahn = gbuf[(255 + u) * GP + b];
            float r = sigf(air + ahr);
            float z = sigf(aiz + ahz);
            float n = tanh_f(fmaf(r, ahn, ain));
            float hold = h2cur[b * HP + u];
            float hnew = n + z * (hold - n);
            h2nxt[b * HP + u] = hnew;
            atomicAdd(&oa_w[b], cWl[u] * hnew);
        }
        __syncthreads();
    }

    if (tid < BB) {
        out[(size_t)(gb0 + tid) * TOT + (TOT - 1)] = oacc[((TOT - 1) & 1) * BB + tid] + blin;
    }
}

extern "C" void kernel_launch(void* const* d_in, const int* in_sizes, int n_in,
                              void* d_out, int out_size) {
    const float* input = (const float*)d_in[0];
    const float* w_ih1 = (const float*)d_in[2];
    const float* w_hh1 = (const float*)d_in[3];
    const float* b_ih1 = (const float*)d_in[4];
    const float* b_hh1 = (const float*)d_in[5];
    const float* w_ih2 = (const float*)d_in[6];
    const float* w_hh2 = (const float*)d_in[7];
    const float* b_ih2 = (const float*)d_in[8];
    const float* b_hh2 = (const float*)d_in[9];
    const float* w_lin = (const float*)d_in[10];
    const float* b_lin = (const float*)d_in[11];

    const int B   = 2048;
    const int T   = in_sizes[0] / B;
    const int TOT = out_size / B;
    const int F   = TOT - T;

    size_t smem = (size_t)(4 * BB * HP + NROWS * GP + BB + 2 * BB + 3 * H) * sizeof(float);
    cudaFuncSetAttribute(gru2_kernel, cudaFuncAttributeMaxDynamicSharedMemorySize, (int)smem);

    gru2_kernel<<<B / BB, NTHREADS, smem>>>(
        input, w_ih1, w_hh1, b_ih1, b_hh1,
        w_ih2, w_hh2, b_ih2, b_hh2,
        w_lin, b_lin, (float*)d_out, T, F);
}

// round 4
// speedup vs baseline: 1.9585x; 1.6931x over previous
#include <cuda_runtime.h>

#define H 51
#define BB 16
#define NROWS 459        // 153 whh1 + 153 whh2 + 153 wih2
#define NTHREADS 512
#define GPU 9            // gbuf pitch (ull)
#define GPF 18           // gbuf pitch (floats)
#define HSTRIDE 816      // floats per h buffer: [51][16]
#define NPW 816          // pointwise tasks per layer (51*16)

typedef unsigned long long ull;

#define FFMA2(d, a, b_) asm("fma.rn.f32x2 %0, %1, %2, %0;" : "+l"(d) : "l"(a), "l"(b_))

__device__ __forceinline__ ull pack2(float lo, float hi) {
    ull r;
    asm("mov.b64 %0, {%1,%2};" : "=l"(r) : "f"(lo), "f"(hi));
    return r;
}
__device__ __forceinline__ float sigf(float v) {
    return __fdividef(1.0f, 1.0f + __expf(-v));
}
__device__ __forceinline__ float tanh_f(float v) {
    return 1.0f - __fdividef(2.0f, __expf(2.0f * v) + 1.0f);
}

__global__ __launch_bounds__(NTHREADS, 1)
void gru2_kernel(const float* __restrict__ input,
                 const float* __restrict__ w_ih1, const float* __restrict__ w_hh1,
                 const float* __restrict__ b_ih1, const float* __restrict__ b_hh1,
                 const float* __restrict__ w_ih2, const float* __restrict__ w_hh2,
                 const float* __restrict__ b_ih2, const float* __restrict__ b_hh2,
                 const float* __restrict__ w_lin, const float* __restrict__ b_lin,
                 float* __restrict__ out, int T, int F)
{
    extern __shared__ float sm[];
    float* hT1   = sm;                         // [2][51][16]  h1, k-major transposed
    float* hT2   = hT1 + 2 * HSTRIDE;          // [2][51][16]  h2
    ull*   gbufU = (ull*)(sm + 4 * HSTRIDE);   // [459][9]
    float* gbufF = (float*)gbufU;
    float* tabs  = (float*)(gbufU + NROWS * GPU);  // w1r|w1z|w1n|c1r|c1z|c1n|wl : 7*51
    float* xbuf  = tabs + 7 * H;               // [16]
    float* oacc  = xbuf + BB;                  // [2][16]

    const int tid = threadIdx.x;
    const int gb0 = blockIdx.x * BB;
    const int TOT = T + F;

    for (int i = tid; i < 4 * HSTRIDE; i += NTHREADS) sm[i] = 0.f;
    if (tid < H) {
        tabs[tid]         = __ldg(&w_ih1[tid]);
        tabs[H + tid]     = __ldg(&w_ih1[H + tid]);
        tabs[2 * H + tid] = __ldg(&w_ih1[2 * H + tid]);
        tabs[3 * H + tid] = __ldg(&b_ih1[tid]);
        tabs[4 * H + tid] = __ldg(&b_ih1[H + tid]);
        tabs[5 * H + tid] = __ldg(&b_ih1[2 * H + tid]);
        tabs[6 * H + tid] = __ldg(&w_lin[tid]);
    }
    if (tid < 2 * BB) oacc[tid] = 0.f;

    // Per-thread row weights -> 51 registers
    const float* wsrc = w_hh1;
    float b0 = 0.f;
    int hsel = 0;        // 0: reads hT1[(i+1)&1], 1: reads hT2[i&1]
    if (tid < 153)      { wsrc = w_hh1 + tid * H;        b0 = __ldg(&b_hh1[tid]);       hsel = 0; }
    else if (tid < 306) { wsrc = w_hh2 + (tid - 153) * H; b0 = __ldg(&b_hh2[tid - 153]); hsel = 1; }
    else if (tid < 459) { wsrc = w_ih2 + (tid - 306) * H; b0 = __ldg(&b_ih2[tid - 306]); hsel = 0; }
    float w[51];
    #pragma unroll
    for (int j = 0; j < 51; ++j) w[j] = __ldg(&wsrc[j]);
    const ull bias2 = pack2(b0, b0);
    const float blin = __ldg(&b_lin[0]);
    const int pxor = hsel ? 0 : 1;
    const float* hbase = hsel ? hT2 : hT1;

    __syncthreads();

    for (int i = 0; i <= TOT; ++i) {
        const int par = i & 1;

        // ================= DOT STAGE (all 459 rows) =================
        if (tid < NROWS) {
            const float* hp = hbase + ((par ^ pxor) * HSTRIDE);
            ull acc[8];
            #pragma unroll
            for (int bp = 0; bp < 8; ++bp) acc[bp] = bias2;
            #pragma unroll
            for (int k = 0; k < 51; ++k) {
                const ull wd = pack2(w[k], w[k]);
                const ulonglong2* q = (const ulonglong2*)(hp + k * 16);
                ulonglong2 q0 = q[0], q1 = q[1], q2 = q[2], q3 = q[3];
                FFMA2(acc[0], wd, q0.x); FFMA2(acc[1], wd, q0.y);
                FFMA2(acc[2], wd, q1.x); FFMA2(acc[3], wd, q1.y);
                FFMA2(acc[4], wd, q2.x); FFMA2(acc[5], wd, q2.y);
                FFMA2(acc[6], wd, q3.x); FFMA2(acc[7], wd, q3.y);
            }
            ull* go = gbufU + tid * GPU;
            #pragma unroll
            for (int bp = 0; bp < 8; ++bp) go[bp] = acc[bp];
        } else {
            int j = tid - NROWS;
            if (j < BB) {
                if (i >= 2) out[(size_t)(gb0 + j) * TOT + (i - 2)] = oacc[((i - 1) & 1) * BB + j] + blin;
                oacc[par * BB + j] = 0.f;
                if (i < T) xbuf[j] = __ldg(&input[(size_t)(gb0 + j) * T + i]);
            }
        }
        __syncthreads();

        // ================= POINTWISE STAGE =================
        float* oa    = oacc + par * BB;
        float* h2c   = hT2 + par * HSTRIDE;          // h2[i-2]
        float* h2n   = hT2 + (par ^ 1) * HSTRIDE;    // h2[i-1]
        float* h1c   = hT1 + (par ^ 1) * HSTRIDE;    // h1[i-1]
        float* h1n   = hT1 + par * HSTRIDE;          // h1[i]

        if (i < T) {
            // main mode: fused L2 + L1 pointwise, one barrier
            for (int j = tid; j < 2 * NPW; j += NTHREADS) {
                if (j < NPW) {
                    if (i > 0) {
                        int u = j >> 4, b = j & 15;
                        float dir = gbufF[(306 + u) * GPF + b];
                        float diz = gbufF[(357 + u) * GPF + b];
                        float din = gbufF[(408 + u) * GPF + b];
                        float d2r = gbufF[(153 + u) * GPF + b];
                        float d2z = gbufF[(204 + u) * GPF + b];
                        float d2n = gbufF[(255 + u) * GPF + b];
                        float r = sigf(dir + d2r);
                        float z = sigf(diz + d2z);
                        float n = tanh_f(fmaf(r, d2n, din));
                        float hold = h2c[u * 16 + b];
                        float hnew = n + z * (hold - n);
                        h2n[u * 16 + b] = hnew;
                        atomicAdd(&oa[b], tabs[6 * H + u] * hnew);
                    }
                } else {
                    int jj = j - NPW;
                    int u = jj >> 4, b = jj & 15;
                    float x = xbuf[b];
                    float ar = gbufF[u * GPF + b];
                    float az = gbufF[(51 + u) * GPF + b];
                    float an = gbufF[(102 + u) * GPF + b];
                    float r = sigf(fmaf(x, tabs[u], tabs[3 * H + u]) + ar);
                    float z = sigf(fmaf(x, tabs[H + u], tabs[4 * H + u]) + az);
                    float n = tanh_f(fmaf(x, tabs[2 * H + u], tabs[5 * H + u]) + r * an);
                    float hold = h1c[u * 16 + b];
                    h1n[u * 16 + b] = n + z * (hold - n);
                }
            }
            __syncthreads();
        } else {
            // future mode: L2 (+o reduction) -> sync -> L1 (x = o[i-1]+blin)
            for (int j = tid; j < NPW; j += NTHREADS) {
                int u = j >> 4, b = j & 15;
                float dir = gbufF[(306 + u) * GPF + b];
                float diz = gbufF[(357 + u) * GPF + b];
                float din = gbufF[(408 + u) * GPF + b];
                float d2r = gbufF[(153 + u) * GPF + b];
                float d2z = gbufF[(204 + u) * GPF + b];
                float d2n = gbufF[(255 + u) * GPF + b];
                float r = sigf(dir + d2r);
                float z = sigf(diz + d2z);
                float n = tanh_f(fmaf(r, d2n, din));
                float hold = h2c[u * 16 + b];
                float hnew = n + z * (hold - n);
                h2n[u * 16 + b] = hnew;
                atomicAdd(&oa[b], tabs[6 * H + u] * hnew);
            }
            __syncthreads();
            for (int j = tid; j < NPW; j += NTHREADS) {
                int u = j >> 4, b = j & 15;
                float x = oa[b] + blin;
                float ar = gbufF[u * GPF + b];
                float az = gbufF[(51 + u) * GPF + b];
                float an = gbufF[(102 + u) * GPF + b];
                float r = sigf(fmaf(x, tabs[u], tabs[3 * H + u]) + ar);
                float z = sigf(fmaf(x, tabs[H + u], tabs[4 * H + u]) + az);
                float n = tanh_f(fmaf(x, tabs[2 * H + u], tabs[5 * H + u]) + r * an);
                float hold = h1c[u * 16 + b];
                h1n[u * 16 + b] = n + z * (hold - n);
            }
            __syncthreads();
        }
    }

    if (tid < BB)
        out[(size_t)(gb0 + tid) * TOT + (TOT - 1)] = oacc[(TOT & 1) * BB + tid] + blin;
}

extern "C" void kernel_launch(void* const* d_in, const int* in_sizes, int n_in,
                              void* d_out, int out_size) {
    const float* input = (const float*)d_in[0];
    const float* w_ih1 = (const float*)d_in[2];
    const float* w_hh1 = (const float*)d_in[3];
    const float* b_ih1 = (const float*)d_in[4];
    const float* b_hh1 = (const float*)d_in[5];
    const float* w_ih2 = (const float*)d_in[6];
    const float* w_hh2 = (const float*)d_in[7];
    const float* b_ih2 = (const float*)d_in[8];
    const float* b_hh2 = (const float*)d_in[9];
    const float* w_lin = (const float*)d_in[10];
    const float* b_lin = (const float*)d_in[11];

    const int B   = 2048;
    const int T   = in_sizes[0] / B;
    const int TOT = out_size / B;
    const int F   = TOT - T;

    size_t smem = (size_t)(4 * HSTRIDE * 4 + NROWS * GPU * 8 + (7 * H + BB + 2 * BB) * 4);
    cudaFuncSetAttribute(gru2_kernel, cudaFuncAttributeMaxDynamicSharedMemorySize, (int)smem);

    gru2_kernel<<<B / BB, NTHREADS, smem>>>(
        input, w_ih1, w_hh1, b_ih1, b_hh1,
        w_ih2, w_hh2, b_ih2, b_hh2,
        w_lin, b_lin, (float*)d_out, T, F);
}